// round 17
// baseline (speedup 1.0000x reference)
#include <cuda_runtime.h>
#include <cuda_bf16.h>
#include <math.h>

#define N_NODES 50000
#define N_EDGES 800000
#define DIM_IN  128
#define DIM_H   64
#define DIM_OUT 16

// Scratch (allocation-free: __device__ globals)
__device__ __align__(16) float g_A[N_NODES * DIM_H];    // gemm1 out
__device__ __align__(16) float g_C[N_NODES * DIM_OUT];  // fused spmm64+tanh+W23 out
__device__ __align__(16) float g_U[N_NODES * DIM_OUT];  // spmm16 #1 out
__device__ __align__(16) float g_W23[DIM_H * DIM_OUT];  // W2@W3

// CSR build scratch
__device__ int  g_cnt[N_NODES];
__device__ int  g_cur[N_NODES];
__device__ int  g_rowptr[N_NODES + 1];
__device__ int  g_bsum[256];
__device__ __align__(8) int2 g_spack[N_EDGES];  // dst-sorted (src, val_bits)

// ---------------------------------------------------------------------------
// Merged: zero histogram + W23 = W2@W3 (independent prologue work)
// ---------------------------------------------------------------------------
__global__ void zw_kernel(int* __restrict__ cnt, int n,
                          const float* __restrict__ W2,
                          const float* __restrict__ W3,
                          float* __restrict__ W23) {
    int i = blockIdx.x * blockDim.x + threadIdx.x;
    if (i < n) cnt[i] = 0;
    if (i < DIM_H * DIM_OUT) {
        int r = i / DIM_OUT, c = i % DIM_OUT;
        float s = 0.f;
        #pragma unroll 8
        for (int k = 0; k < DIM_H; k++)
            s = fmaf(W2[r * DIM_H + k], W3[k * DIM_OUT + c], s);
        W23[i] = s;
    }
}

// ---------------------------------------------------------------------------
// CSR build: histogram of dst
// ---------------------------------------------------------------------------
__global__ void hist_kernel(const int* __restrict__ dst, int* __restrict__ cnt, int E) {
    int e = blockIdx.x * blockDim.x + threadIdx.x;
    if (e < E) atomicAdd(&cnt[dst[e]], 1);
}

// ---------------------------------------------------------------------------
// CSR build: per-block exclusive scan (512/block), block totals out
// ---------------------------------------------------------------------------
__global__ void scan1_kernel(const int* __restrict__ cnt, int* __restrict__ rowptr,
                             int* __restrict__ bsum, int n) {
    __shared__ int sh[512];
    int tid = threadIdx.x;
    int i = blockIdx.x * 512 + tid;
    int v = (i < n) ? cnt[i] : 0;
    sh[tid] = v;
    __syncthreads();
    #pragma unroll
    for (int off = 1; off < 512; off <<= 1) {
        int t = (tid >= off) ? sh[tid - off] : 0;
        __syncthreads();
        sh[tid] += t;
        __syncthreads();
    }
    if (i < n) rowptr[i] = sh[tid] - v;   // exclusive within block
    if (tid == 511) bsum[blockIdx.x] = sh[511];
}

// ---------------------------------------------------------------------------
// CSR build: merged scan2+scan3 (per-block offset reduce + apply + cursors)
// ---------------------------------------------------------------------------
__global__ void scan23_kernel(int* __restrict__ rowptr, const int* __restrict__ bsum,
                              int* __restrict__ cur, int n, int E) {
    __shared__ int sh[256];
    int tid = threadIdx.x;
    int bneed = blockIdx.x >> 1;          // # of preceding 512-blocks
    sh[tid] = (tid < bneed) ? bsum[tid] : 0;
    __syncthreads();
    #pragma unroll
    for (int off = 128; off > 0; off >>= 1) {
        if (tid < off) sh[tid] += sh[tid + off];
        __syncthreads();
    }
    int offset = sh[0];
    int i = blockIdx.x * 256 + tid;
    if (i < n) {
        int v = rowptr[i] + offset;
        rowptr[i] = v;
        cur[i] = v;
    }
    if (blockIdx.x == 0 && tid == 0) rowptr[n] = E;
}

// ---------------------------------------------------------------------------
// CSR build: scatter edges into dst-sorted pack
// ---------------------------------------------------------------------------
__global__ void scatter_kernel(const int* __restrict__ src, const int* __restrict__ dst,
                               const float* __restrict__ val, int* __restrict__ cur,
                               int2* __restrict__ spack, int E) {
    int e = blockIdx.x * blockDim.x + threadIdx.x;
    if (e >= E) return;
    int d = dst[e];
    int p = atomicAdd(&cur[d], 1);
    spack[p] = make_int2(src[e], __float_as_int(val[e]));
}

// ---------------------------------------------------------------------------
// GEMM1: out[n,64] = in[n,128] @ W[128,64].
// 128 threads; 64 nodes/block; thread = 4 nodes x 8 cols; 48KB static smem.
// ---------------------------------------------------------------------------
template <int DIN, int DOUT>
__global__ void gemm_tiled48(const float* __restrict__ in,
                             const float* __restrict__ W,
                             float* __restrict__ out, int n) {
    constexpr int OCTS  = DOUT / 8;       // 8
    constexpr int NPB   = (128 / OCTS) * 4;  // 64 nodes/block
    constexpr int KT    = 64;             // k-tile
    constexpr int NKT   = DIN / KT;       // 2
    constexpr int WQ    = DOUT / 4;       // float4s per W row

    __shared__ __align__(16) float Ws[DIN * DOUT];   // 32KB
    __shared__ __align__(16) float xs[KT][NPB];      // 16KB

    const int tid = threadIdx.x;
    const int node0 = blockIdx.x * NPB;

    #pragma unroll 4
    for (int i = tid; i < DIN * DOUT / 4; i += 128)
        reinterpret_cast<float4*>(Ws)[i] = reinterpret_cast<const float4*>(W)[i];

    const int oct   = tid % OCTS;
    const int nbase = (tid / OCTS) * 4;

    float4 acc[4][2] = {};

    for (int kt = 0; kt < NKT; kt++) {
        __syncthreads();   // xs reuse barrier (and W-ready on first iter)
        for (int i = tid; i < NPB * (KT / 4); i += 128) {
            int nn = i / (KT / 4);
            int kk = i % (KT / 4);
            int node = node0 + nn;
            float4 v = make_float4(0.f, 0.f, 0.f, 0.f);
            if (node < n)
                v = reinterpret_cast<const float4*>(in + (size_t)node * DIN)[kt * (KT / 4) + kk];
            xs[kk * 4 + 0][nn] = v.x;
            xs[kk * 4 + 1][nn] = v.y;
            xs[kk * 4 + 2][nn] = v.z;
            xs[kk * 4 + 3][nn] = v.w;
        }
        __syncthreads();

        #pragma unroll 4
        for (int k = 0; k < KT; k++) {
            float4 xv = *reinterpret_cast<const float4*>(&xs[k][nbase]);
            const float4* wr = reinterpret_cast<const float4*>(Ws) + (kt * KT + k) * WQ;
            float4 w0 = wr[oct * 2];
            float4 w1 = wr[oct * 2 + 1];
            float xn[4] = {xv.x, xv.y, xv.z, xv.w};
            #pragma unroll
            for (int i = 0; i < 4; i++) {
                acc[i][0].x = fmaf(xn[i], w0.x, acc[i][0].x);
                acc[i][0].y = fmaf(xn[i], w0.y, acc[i][0].y);
                acc[i][0].z = fmaf(xn[i], w0.z, acc[i][0].z);
                acc[i][0].w = fmaf(xn[i], w0.w, acc[i][0].w);
                acc[i][1].x = fmaf(xn[i], w1.x, acc[i][1].x);
                acc[i][1].y = fmaf(xn[i], w1.y, acc[i][1].y);
                acc[i][1].z = fmaf(xn[i], w1.z, acc[i][1].z);
                acc[i][1].w = fmaf(xn[i], w1.w, acc[i][1].w);
            }
        }
    }

    #pragma unroll
    for (int i = 0; i < 4; i++) {
        int node = node0 + nbase + i;
        if (node < n) {
            float4* o = reinterpret_cast<float4*>(out + (size_t)node * DOUT);
            o[oct * 2]     = acc[i][0];
            o[oct * 2 + 1] = acc[i][1];
        }
    }
}

// ---------------------------------------------------------------------------
// FUSED: CSR SpMM d=64 + tanh + @W23[64,16] epilogue.
// One warp per node; b kept in registers (lane, lane+32); W23 rows read via
// __ldg (4KB table, L1-resident); 16-float butterfly reduce; lane 0 stores C.
// Warp-uniform early exit (warp index identical across lanes) => shfl-safe.
// ---------------------------------------------------------------------------
__global__ void spmm64_tanh_w23(const int* __restrict__ rowptr,
                                const int2* __restrict__ spack,
                                const float* __restrict__ h,
                                const float* __restrict__ W23,
                                float* __restrict__ Cout, int n) {
    int warp = (blockIdx.x * blockDim.x + threadIdx.x) >> 5;
    if (warp >= n) return;                     // warp-uniform
    int lane = threadIdx.x & 31;
    int beg = __ldg(&rowptr[warp]);
    int end = __ldg(&rowptr[warp + 1]);
    float acc0 = 0.f, acc1 = 0.f;
    int j = beg;
    for (; j + 1 < end; j += 2) {
        int2 p0 = __ldg(&spack[j]);
        int2 p1 = __ldg(&spack[j + 1]);
        const float* h0 = h + (size_t)p0.x * 64;
        const float* h1 = h + (size_t)p1.x * 64;
        float v0 = __int_as_float(p0.y);
        float v1 = __int_as_float(p1.y);
        float a0 = __ldg(h0 + lane);
        float b0 = __ldg(h0 + lane + 32);
        float a1 = __ldg(h1 + lane);
        float b1 = __ldg(h1 + lane + 32);
        acc0 = fmaf(v0, a0, acc0);
        acc1 = fmaf(v0, b0, acc1);
        acc0 = fmaf(v1, a1, acc0);
        acc1 = fmaf(v1, b1, acc1);
    }
    if (j < end) {
        int2 p = __ldg(&spack[j]);
        const float* hr = h + (size_t)p.x * 64;
        float v = __int_as_float(p.y);
        acc0 = fmaf(v, __ldg(hr + lane), acc0);
        acc1 = fmaf(v, __ldg(hr + lane + 32), acc1);
    }
    // epilogue: C[warp][:] = sum_lanes tanh(b_lane)*W23[lane][:] + tanh(b_lane+32)*W23[lane+32][:]
    float t0 = tanhf(acc0);
    float t1 = tanhf(acc1);
    const float4* w0 = reinterpret_cast<const float4*>(W23 + lane * DIM_OUT);
    const float4* w1 = reinterpret_cast<const float4*>(W23 + (lane + 32) * DIM_OUT);
    float4 p[4];
    #pragma unroll
    for (int q = 0; q < 4; q++) {
        float4 a = __ldg(w0 + q);
        float4 b = __ldg(w1 + q);
        p[q].x = fmaf(t0, a.x, t1 * b.x);
        p[q].y = fmaf(t0, a.y, t1 * b.y);
        p[q].z = fmaf(t0, a.z, t1 * b.z);
        p[q].w = fmaf(t0, a.w, t1 * b.w);
    }
    #pragma unroll
    for (int mask = 16; mask > 0; mask >>= 1) {
        #pragma unroll
        for (int q = 0; q < 4; q++) {
            p[q].x += __shfl_xor_sync(0xFFFFFFFFu, p[q].x, mask);
            p[q].y += __shfl_xor_sync(0xFFFFFFFFu, p[q].y, mask);
            p[q].z += __shfl_xor_sync(0xFFFFFFFFu, p[q].z, mask);
            p[q].w += __shfl_xor_sync(0xFFFFFFFFu, p[q].w, mask);
        }
    }
    if (lane == 0) {
        float4* o = reinterpret_cast<float4*>(Cout + (size_t)warp * DIM_OUT);
        o[0] = p[0]; o[1] = p[1]; o[2] = p[2]; o[3] = p[3];
    }
}

// ---------------------------------------------------------------------------
// CSR SpMM d=16: 16 threads per node. No atomics.
// ---------------------------------------------------------------------------
__global__ void spmm16_csr(const int* __restrict__ rowptr,
                           const int2* __restrict__ spack,
                           const float* __restrict__ h,
                           float* __restrict__ out, int n) {
    int g = blockIdx.x * blockDim.x + threadIdx.x;
    int node = g >> 4;
    if (node >= n) return;
    int f = g & 15;
    int beg = __ldg(&rowptr[node]);
    int end = __ldg(&rowptr[node + 1]);
    float acc = 0.f;
    int j = beg;
    for (; j + 1 < end; j += 2) {
        int2 p0 = __ldg(&spack[j]);
        int2 p1 = __ldg(&spack[j + 1]);
        float a0 = __ldg(h + (size_t)p0.x * 16 + f);
        float a1 = __ldg(h + (size_t)p1.x * 16 + f);
        acc = fmaf(__int_as_float(p0.y), a0, acc);
        acc = fmaf(__int_as_float(p1.y), a1, acc);
    }
    if (j < end) {
        int2 p = __ldg(&spack[j]);
        acc = fmaf(__int_as_float(p.y), __ldg(h + (size_t)p.x * 16 + f), acc);
    }
    out[(size_t)node * 16 + f] = acc;
}

// ---------------------------------------------------------------------------
// CSR SpMM d=16 + fused softmax over the 16 lanes of each node group.
// All threads stay active for shfl safety (invalid nodes compute on zeros).
// ---------------------------------------------------------------------------
__global__ void spmm16_softmax(const int* __restrict__ rowptr,
                               const int2* __restrict__ spack,
                               const float* __restrict__ h,
                               float* __restrict__ out, int n) {
    int g = blockIdx.x * blockDim.x + threadIdx.x;
    int node = g >> 4;
    int f = g & 15;
    bool valid = node < n;
    int beg = 0, end = 0;
    if (valid) {
        beg = __ldg(&rowptr[node]);
        end = __ldg(&rowptr[node + 1]);
    }
    float acc = 0.f;
    int j = beg;
    for (; j + 1 < end; j += 2) {
        int2 p0 = __ldg(&spack[j]);
        int2 p1 = __ldg(&spack[j + 1]);
        float a0 = __ldg(h + (size_t)p0.x * 16 + f);
        float a1 = __ldg(h + (size_t)p1.x * 16 + f);
        acc = fmaf(__int_as_float(p0.y), a0, acc);
        acc = fmaf(__int_as_float(p1.y), a1, acc);
    }
    if (j < end) {
        int2 p = __ldg(&spack[j]);
        acc = fmaf(__int_as_float(p.y), __ldg(h + (size_t)p.x * 16 + f), acc);
    }
    // softmax across the 16-lane group (xor masks < 16 stay within the group)
    float m = acc;
    #pragma unroll
    for (int mask = 8; mask > 0; mask >>= 1)
        m = fmaxf(m, __shfl_xor_sync(0xFFFFFFFFu, m, mask));
    float e = __expf(acc - m);
    float s = e;
    #pragma unroll
    for (int mask = 8; mask > 0; mask >>= 1)
        s += __shfl_xor_sync(0xFFFFFFFFu, s, mask);
    if (valid)
        out[(size_t)node * 16 + f] = e / s;
}

// ---------------------------------------------------------------------------
// Launch
// ---------------------------------------------------------------------------
extern "C" void kernel_launch(void* const* d_in, const int* in_sizes, int n_in,
                              void* d_out, int out_size) {
    const float* x        = (const float*)d_in[0];
    const int*   edge_src = (const int*)d_in[1];
    const int*   edge_dst = (const int*)d_in[2];
    const float* edge_val = (const float*)d_in[3];
    const float* W1       = (const float*)d_in[4];
    const float* W2       = (const float*)d_in[5];
    const float* W3       = (const float*)d_in[6];
    float* out = (float*)d_out;

    const int N = in_sizes[0] / DIM_IN;   // 50000
    const int E = in_sizes[1];            // 800000

    float *A, *C, *U, *W23;
    int *cnt, *cur, *rowptr, *bsum;
    int2 *spack;
    cudaGetSymbolAddress((void**)&A, g_A);
    cudaGetSymbolAddress((void**)&C, g_C);
    cudaGetSymbolAddress((void**)&U, g_U);
    cudaGetSymbolAddress((void**)&W23, g_W23);
    cudaGetSymbolAddress((void**)&cnt, g_cnt);
    cudaGetSymbolAddress((void**)&cur, g_cur);
    cudaGetSymbolAddress((void**)&rowptr, g_rowptr);
    cudaGetSymbolAddress((void**)&bsum, g_bsum);
    cudaGetSymbolAddress((void**)&spack, g_spack);

    // 1. zero hist + W23 (merged)
    zw_kernel<<<(N + 255) / 256, 256>>>(cnt, N, W2, W3, W23);
    // 2. histogram of dst
    hist_kernel<<<(E + 255) / 256, 256>>>(edge_dst, cnt, E);
    // 3. per-block scan
    scan1_kernel<<<(N + 511) / 512, 512>>>(cnt, rowptr, bsum, N);
    // 4. merged block-offset apply + cursor init
    scan23_kernel<<<(N + 255) / 256, 256>>>(rowptr, bsum, cur, N, E);
    // 5. scatter into dst-sorted pack
    scatter_kernel<<<(E + 255) / 256, 256>>>(edge_src, edge_dst, edge_val, cur, spack, E);

    // 6. A = x @ W1
    gemm_tiled48<DIM_IN, DIM_H><<<(N + 63) / 64, 128>>>(x, W1, A, N);
    // 7. C = tanh(spmm(A)) @ W23   [FUSED: spmm64 + tanh + W23 epilogue]
    spmm64_tanh_w23<<<(N * 32 + 255) / 256, 256>>>(rowptr, spack, A, W23, C, N);
    // 8. U = spmm(C)   [d=16, CSR]
    spmm16_csr<<<(N * 16 + 255) / 256, 256>>>(rowptr, spack, C, U, N);
    // 9. out = softmax(spmm(U))   [d=16, CSR + fused softmax]
    spmm16_softmax<<<(N * 16 + 255) / 256, 256>>>(rowptr, spack, U, out, N);
}